// round 1
// baseline (speedup 1.0000x reference)
#include <cuda_runtime.h>
#include <cuda_bf16.h>

// Problem constants
#define BB   2048
#define MAXN 16
#define NVTT 8
#define HS   501
#define VS   517      // HS + MAXN
#define H3   1503     // 3*HS
#define H2   1002     // 2*HS
#define NZ   56

// ---------------- scratch (device globals; no allocation) ----------------
__device__ float d_W2[H2 * HS];        // packed [gate_w[:, :HS]; map_w[:, :HS]]
__device__ float d_Hin[BB * HS];       // h_in per step
__device__ float d_GH[BB * H3];        // h_in @ w_hh^T
__device__ float d_hv[BB * HS];        // GRU output per step
__device__ float d_GM[BB * H2];        // hv @ [gw_h; mw_h]^T
__device__ float d_M[BB * MAXN * HS];  // memory bank M

// ---------------- pack W2 ----------------
__global__ void pack_w2_kernel(const float* __restrict__ gate_w,
                               const float* __restrict__ map_w) {
    int idx = blockIdx.x * blockDim.x + threadIdx.x;
    if (idx >= H2 * HS) return;
    int n = idx / HS;
    int k = idx - n * HS;
    float v;
    if (n < HS) v = gate_w[n * VS + k];
    else        v = map_w[(n - HS) * VS + k];
    d_W2[idx] = v;
}

// ---------------- h_in = sum_{n<v} adj[b,v,n] * M[b,n,:] ----------------
__global__ void hin_kernel(const float* __restrict__ adj, int v) {
    int b = blockIdx.x;
    __shared__ float sa[MAXN];
    if (threadIdx.x < MAXN)
        sa[threadIdx.x] = adj[(b * MAXN + v) * MAXN + threadIdx.x];
    __syncthreads();
    const float* Mb = d_M + (size_t)b * MAXN * HS;
    for (int j = threadIdx.x; j < HS; j += blockDim.x) {
        float acc = 0.f;
        #pragma unroll
        for (int n = 0; n < MAXN; n++) {
            if (n < v) acc += sa[n] * Mb[n * HS + j];
        }
        d_Hin[b * HS + j] = acc;
    }
}

// ---------------- SGEMM: C[2048,N] = A[2048,K=501] @ W[N,K=501]^T ----------------
#define BM 128
#define BN 128
#define BK 16

__global__ void __launch_bounds__(256, 2)
sgemm_tn(const float* __restrict__ A, const float* __restrict__ W,
         float* __restrict__ C, int N) {
    __shared__ float As[BK][BM + 4];
    __shared__ float Ws[BK][BN + 4];
    const int K = HS;
    int tid = threadIdx.x;
    int rowBase = blockIdx.y * BM;
    int colBase = blockIdx.x * BN;

    int lk = tid & 15;   // k within tile
    int lr = tid >> 4;   // base row within tile
    int tx = tid & 15;   // 0..15 -> 8 output cols each
    int ty = tid >> 4;   // 0..15 -> 8 output rows each

    float acc[8][8];
    #pragma unroll
    for (int i = 0; i < 8; i++)
        #pragma unroll
        for (int j = 0; j < 8; j++) acc[i][j] = 0.f;

    float pa[8], pw[8];
    int k0 = 0;
    // prefetch first tile
    {
        int gk = k0 + lk;
        bool kok = (gk < K);
        #pragma unroll
        for (int i = 0; i < 8; i++) {
            int r = lr + 16 * i;
            pa[i] = kok ? A[(size_t)(rowBase + r) * K + gk] : 0.f;
            int n = colBase + r;
            pw[i] = (kok && n < N) ? W[(size_t)n * K + gk] : 0.f;
        }
    }
    for (;;) {
        #pragma unroll
        for (int i = 0; i < 8; i++) {
            As[lk][lr + 16 * i] = pa[i];
            Ws[lk][lr + 16 * i] = pw[i];
        }
        __syncthreads();

        int knext = k0 + BK;
        if (knext < K) {
            int gk = knext + lk;
            bool kok = (gk < K);
            #pragma unroll
            for (int i = 0; i < 8; i++) {
                int r = lr + 16 * i;
                pa[i] = kok ? A[(size_t)(rowBase + r) * K + gk] : 0.f;
                int n = colBase + r;
                pw[i] = (kok && n < N) ? W[(size_t)n * K + gk] : 0.f;
            }
        }

        #pragma unroll
        for (int kk = 0; kk < BK; kk++) {
            float af[8], wf[8];
            const float4* a4 = reinterpret_cast<const float4*>(&As[kk][ty * 8]);
            const float4* w4 = reinterpret_cast<const float4*>(&Ws[kk][tx * 8]);
            float4 a0 = a4[0], a1 = a4[1];
            float4 w0 = w4[0], w1 = w4[1];
            af[0]=a0.x; af[1]=a0.y; af[2]=a0.z; af[3]=a0.w;
            af[4]=a1.x; af[5]=a1.y; af[6]=a1.z; af[7]=a1.w;
            wf[0]=w0.x; wf[1]=w0.y; wf[2]=w0.z; wf[3]=w0.w;
            wf[4]=w1.x; wf[5]=w1.y; wf[6]=w1.z; wf[7]=w1.w;
            #pragma unroll
            for (int i = 0; i < 8; i++)
                #pragma unroll
                for (int j = 0; j < 8; j++)
                    acc[i][j] += af[i] * wf[j];
        }
        __syncthreads();
        k0 = knext;
        if (k0 >= K) break;
    }

    #pragma unroll
    for (int i = 0; i < 8; i++) {
        int r = rowBase + ty * 8 + i;
        #pragma unroll
        for (int j = 0; j < 8; j++) {
            int n = colBase + tx * 8 + j;
            if (n < N) C[(size_t)r * N + n] = acc[i][j];
        }
    }
}

// ---------------- GRU gate epilogue: hv from GH + gathered gi ----------------
__global__ void epi1_kernel(const int* __restrict__ node_types,
                            const float* __restrict__ w_ih,
                            const float* __restrict__ b_ih,
                            const float* __restrict__ b_hh, int v) {
    int idx = blockIdx.x * blockDim.x + threadIdx.x;
    if (idx >= BB * HS) return;
    int b = idx / HS;
    int j = idx - b * HS;
    int t = node_types[b * MAXN + v];
    float ir  = w_ih[(size_t)j * NVTT + t]            + b_ih[j];
    float iz  = w_ih[(size_t)(j + HS) * NVTT + t]     + b_ih[j + HS];
    float inn = w_ih[(size_t)(j + 2 * HS) * NVTT + t] + b_ih[j + 2 * HS];
    const float* gh = d_GH + (size_t)b * H3;
    float hr = gh[j]          + b_hh[j];
    float hz = gh[j + HS]     + b_hh[j + HS];
    float hn = gh[j + 2 * HS] + b_hh[j + 2 * HS];
    float r = 1.f / (1.f + expf(-(ir + hr)));
    float z = 1.f / (1.f + expf(-(iz + hz)));
    float n = tanhf(inn + r * hn);
    float h = d_Hin[idx];
    d_hv[idx] = (1.f - z) * n + z * h;
}

// ---------------- gate/map epilogue: M[b,v,:] = sigmoid(g)*m ----------------
__global__ void epi2_kernel(const float* __restrict__ gate_w,
                            const float* __restrict__ gate_b,
                            const float* __restrict__ map_w, int v) {
    int idx = blockIdx.x * blockDim.x + threadIdx.x;
    if (idx >= BB * HS) return;
    int b = idx / HS;
    int j = idx - b * HS;
    float g = d_GM[(size_t)b * H2 + j] + gate_w[(size_t)j * VS + HS + v] + gate_b[j];
    g = 1.f / (1.f + expf(-g));
    float m = d_GM[(size_t)b * H2 + HS + j] + map_w[(size_t)j * VS + HS + v];
    d_M[((size_t)b * MAXN + v) * HS + j] = g * m;
}

// ---------------- final head: out = [hg@fc1^T+b1, hg@fc2^T+b2] ----------------
__global__ void final_kernel(const float* __restrict__ fc1_w,
                             const float* __restrict__ fc1_b,
                             const float* __restrict__ fc2_w,
                             const float* __restrict__ fc2_b,
                             float* __restrict__ out) {
    int b = blockIdx.x;
    __shared__ float sh[HS];
    for (int j = threadIdx.x; j < HS; j += blockDim.x)
        sh[j] = d_hv[(size_t)b * HS + j];
    __syncthreads();
    int o = threadIdx.x;
    if (o < 2 * NZ) {
        const float* w;
        float bias;
        if (o < NZ) { w = fc1_w + (size_t)o * HS;        bias = fc1_b[o]; }
        else        { w = fc2_w + (size_t)(o - NZ) * HS; bias = fc2_b[o - NZ]; }
        float acc = bias;
        #pragma unroll 4
        for (int k = 0; k < HS; k++) acc += w[k] * sh[k];
        out[(size_t)b * (2 * NZ) + o] = acc;
    }
}

// ---------------- launch ----------------
extern "C" void kernel_launch(void* const* d_in, const int* in_sizes, int n_in,
                              void* d_out, int out_size) {
    const int*   node_types = (const int*)  d_in[0];
    const float* adj        = (const float*)d_in[1];
    const float* w_ih       = (const float*)d_in[2];
    const float* w_hh       = (const float*)d_in[3];
    const float* b_ih       = (const float*)d_in[4];
    const float* b_hh       = (const float*)d_in[5];
    const float* gate_w     = (const float*)d_in[6];
    const float* gate_b     = (const float*)d_in[7];
    const float* map_w      = (const float*)d_in[8];
    const float* fc1_w      = (const float*)d_in[9];
    const float* fc1_b      = (const float*)d_in[10];
    const float* fc2_w      = (const float*)d_in[11];
    const float* fc2_b      = (const float*)d_in[12];
    float* out = (float*)d_out;

    void *pHin_, *pGH_, *phv_, *pGM_, *pW2_;
    cudaGetSymbolAddress(&pHin_, d_Hin);
    cudaGetSymbolAddress(&pGH_,  d_GH);
    cudaGetSymbolAddress(&phv_,  d_hv);
    cudaGetSymbolAddress(&pGM_,  d_GM);
    cudaGetSymbolAddress(&pW2_,  d_W2);
    float* pHin = (float*)pHin_;
    float* pGH  = (float*)pGH_;
    float* phv  = (float*)phv_;
    float* pGM  = (float*)pGM_;
    float* pW2  = (float*)pW2_;

    pack_w2_kernel<<<(H2 * HS + 255) / 256, 256>>>(gate_w, map_w);

    dim3 g1((H3 + BN - 1) / BN, BB / BM);  // 12 x 16
    dim3 g2((H2 + BN - 1) / BN, BB / BM);  // 8 x 16
    int ew_blocks = (BB * HS + 255) / 256;

    for (int v = 0; v < MAXN; v++) {
        hin_kernel<<<BB, 256>>>(adj, v);
        sgemm_tn<<<g1, 256>>>(pHin, w_hh, pGH, H3);
        epi1_kernel<<<ew_blocks, 256>>>(node_types, w_ih, b_ih, b_hh, v);
        sgemm_tn<<<g2, 256>>>(phv, pW2, pGM, H2);
        epi2_kernel<<<ew_blocks, 256>>>(gate_w, gate_b, map_w, v);
    }
    final_kernel<<<BB, 128>>>(fc1_w, fc1_b, fc2_w, fc2_b, out);
}

// round 3
// speedup vs baseline: 2.5989x; 2.5989x over previous
#include <cuda_runtime.h>
#include <cuda_bf16.h>
#include <cstdint>

// ---------------- problem constants ----------------
#define BB   2048
#define MAXN 16
#define NVTT 8
#define HS   501
#define VS   517
#define HP   512            // padded HS
#define KE   1536           // effective K = 3 * HP (split-bf16 concat)
#define N1P  1536           // padded 3*HS (gate-major, 512 stride)
#define N2P  1024           // padded 2*HS
#define NZ   56

// ---------------- device scratch ----------------
__device__ __nv_bfloat16 d_A2[BB * KE];        // split activation operand
__device__ __nv_bfloat16 d_Whh2[N1P * KE];     // split w_hh (padded, gate-major rows)
__device__ __nv_bfloat16 d_W22[N2P * KE];      // split [gate_w_h ; map_w_h]
__device__ float d_Hin[BB * HP];
__device__ float d_GH[BB * N1P];
__device__ float d_hv[BB * HP];
__device__ float d_GM[BB * N2P];
__device__ float d_M[BB * MAXN * HS];

// ---------------- PTX helpers (sm_80-level only) ----------------
__device__ __forceinline__ uint32_t smem_u32(const void* p) {
    uint32_t a;
    asm("{ .reg .u64 t; cvta.to.shared.u64 t, %1; cvt.u32.u64 %0, t; }" : "=r"(a) : "l"(p));
    return a;
}
__device__ __forceinline__ void cpasync16(uint32_t dst, const void* src) {
    asm volatile("cp.async.cg.shared.global [%0], [%1], 16;" :: "r"(dst), "l"(src) : "memory");
}
#define CP_COMMIT() asm volatile("cp.async.commit_group;" ::: "memory")
#define CP_WAIT1()  asm volatile("cp.async.wait_group 1;" ::: "memory")

__device__ __forceinline__ void ldsm4(uint32_t& r0, uint32_t& r1, uint32_t& r2, uint32_t& r3,
                                      uint32_t addr) {
    asm volatile("ldmatrix.sync.aligned.m8n8.x4.shared.b16 {%0,%1,%2,%3}, [%4];"
                 : "=r"(r0), "=r"(r1), "=r"(r2), "=r"(r3) : "r"(addr));
}
__device__ __forceinline__ void mma_bf16(float& c0, float& c1, float& c2, float& c3,
                                         uint32_t a0, uint32_t a1, uint32_t a2, uint32_t a3,
                                         uint32_t b0, uint32_t b1) {
    asm volatile("mma.sync.aligned.m16n8k16.row.col.f32.bf16.bf16.f32 "
                 "{%0,%1,%2,%3}, {%4,%5,%6,%7}, {%8,%9}, {%0,%1,%2,%3};"
                 : "+f"(c0), "+f"(c1), "+f"(c2), "+f"(c3)
                 : "r"(a0), "r"(a1), "r"(a2), "r"(a3), "r"(b0), "r"(b1));
}

// ---------------- split helpers ----------------
__device__ __forceinline__ void split_bf16(float v, __nv_bfloat16& hi, __nv_bfloat16& lo) {
    hi = __float2bfloat16_rn(v);
    lo = __float2bfloat16_rn(v - __bfloat162float(hi));
}

// ---------------- weight packing ----------------
__global__ void pack_whh_kernel(const float* __restrict__ w_hh) {
    int idx = blockIdx.x * blockDim.x + threadIdx.x;
    if (idx >= N1P * KE) return;
    int np = idx / KE, kp = idx - np * KE;
    int g = np >> 9, j = np & 511;
    int seg = kp >> 9, kk = kp & 511;
    float v = (j < HS && kk < HS) ? w_hh[(g * HS + j) * HS + kk] : 0.f;
    __nv_bfloat16 hi, lo; split_bf16(v, hi, lo);
    d_Whh2[idx] = (seg == 1) ? lo : hi;
}
__global__ void pack_w2_kernel(const float* __restrict__ gate_w,
                               const float* __restrict__ map_w) {
    int idx = blockIdx.x * blockDim.x + threadIdx.x;
    if (idx >= N2P * KE) return;
    int np = idx / KE, kp = idx - np * KE;
    int j = np & 511;
    int seg = kp >> 9, kk = kp & 511;
    float v = 0.f;
    if (j < HS && kk < HS)
        v = (np < 512) ? gate_w[j * VS + kk] : map_w[j * VS + kk];
    __nv_bfloat16 hi, lo; split_bf16(v, hi, lo);
    d_W22[idx] = (seg == 1) ? lo : hi;
}

// ---------------- bf16 HMMA GEMM: C[2048,*] = A2 @ W^T ----------------
// BM=128, BK=64 (128B rows, SW128 swizzle), 3-stage cp.async, 8 warps (2x4)
template <int BN>
__global__ void __launch_bounds__(256, 1)
gemm_tc(const __nv_bfloat16* __restrict__ A, const __nv_bfloat16* __restrict__ W,
        float* __restrict__ C, int ldc) {
    constexpr int BM = 128;
    constexpr int WN = BN / 4;          // warp N tile (48 or 32)
    constexpr int NI = WN / 8;          // n-iters (6 or 4)
    constexpr int NC = KE / 64;         // 24 K-chunks
    constexpr int ABYTES = BM * 128;    // 16 KB
    constexpr int STAGE = (BM + BN) * 128;

    extern __shared__ char dynraw[];
    const uint32_t sbase = smem_u32(dynraw);

    const int tid  = threadIdx.x;
    const int wid  = tid >> 5;
    const int lane = tid & 31;
    const int warpM = wid & 1;          // 0..1
    const int warpN = wid >> 1;         // 0..3
    const int rowBase = blockIdx.y * BM;
    const int colBase = blockIdx.x * BN;

    const __nv_bfloat16* Ab = A + (size_t)rowBase * KE;
    const __nv_bfloat16* Wb = W + (size_t)colBase * KE;

    // per-lane swizzle xor mask (SW128 reduces to this for 128B rows)
    const uint32_t xmask = (uint32_t)((lane & 7) << 4);

    // ldmatrix lane addressing components
    const int a_row = warpM * 64 + (lane & 15);          // + mi*16
    const uint32_t a_coff = (uint32_t)((lane >> 4) << 4);     // 0 or 16
    const int b_row = warpN * WN + (lane & 7) + ((lane >> 4) & 1) * 8; // + ni2*16
    const uint32_t b_coff = (uint32_t)(((lane >> 3) & 1) << 4);

    float acc[4][NI][4];
    #pragma unroll
    for (int i = 0; i < 4; i++)
        #pragma unroll
        for (int j = 0; j < NI; j++)
            #pragma unroll
            for (int q = 0; q < 4; q++) acc[i][j][q] = 0.f;

    // loader: chunk c -> stage buffer s
    auto load_chunk = [&](int c, int s) {
        uint32_t abase = sbase + s * STAGE;
        uint32_t bbase = abase + ABYTES;
        const __nv_bfloat16* ga = Ab + c * 64;
        const __nv_bfloat16* gw = Wb + c * 64;
        #pragma unroll
        for (int i = 0; i < 4; i++) {                // A: 1024 16B ops
            int t = tid + i * 256;
            int row = t >> 3, kk = t & 7;
            cpasync16(abase + row * 128 + ((kk * 16) ^ ((row & 7) << 4)),
                      ga + (size_t)row * KE + kk * 8);
        }
        #pragma unroll
        for (int i = 0; i < BN / 32; i++) {          // B: BN*8 16B ops
            int t = tid + i * 256;
            int row = t >> 3, kk = t & 7;
            cpasync16(bbase + row * 128 + ((kk * 16) ^ ((row & 7) << 4)),
                      gw + (size_t)row * KE + kk * 8);
        }
    };

    auto compute = [&](int s) {
        uint32_t abase = sbase + s * STAGE;
        uint32_t bbase = abase + ABYTES;
        #pragma unroll
        for (int kk = 0; kk < 4; kk++) {             // 4 x k16
            uint32_t kbyte = kk * 32;
            uint32_t af[4][4];
            #pragma unroll
            for (int mi = 0; mi < 4; mi++) {
                uint32_t addr = abase + (a_row + mi * 16) * 128 + ((kbyte + a_coff) ^ xmask);
                ldsm4(af[mi][0], af[mi][1], af[mi][2], af[mi][3], addr);
            }
            uint32_t bf[NI][2];
            #pragma unroll
            for (int nb = 0; nb < NI / 2; nb++) {
                uint32_t addr = bbase + (b_row + nb * 16) * 128 + ((kbyte + b_coff) ^ xmask);
                ldsm4(bf[nb * 2][0], bf[nb * 2][1], bf[nb * 2 + 1][0], bf[nb * 2 + 1][1], addr);
            }
            #pragma unroll
            for (int mi = 0; mi < 4; mi++)
                #pragma unroll
                for (int ni = 0; ni < NI; ni++)
                    mma_bf16(acc[mi][ni][0], acc[mi][ni][1], acc[mi][ni][2], acc[mi][ni][3],
                             af[mi][0], af[mi][1], af[mi][2], af[mi][3],
                             bf[ni][0], bf[ni][1]);
        }
    };

    load_chunk(0, 0); CP_COMMIT();
    load_chunk(1, 1); CP_COMMIT();

    #pragma unroll 1
    for (int c = 0; c < NC; c++) {
        CP_WAIT1();
        __syncthreads();
        if (c + 2 < NC) load_chunk(c + 2, (c + 2) % 3);
        CP_COMMIT();
        compute(c % 3);
    }

    // epilogue: write fp32
    #pragma unroll
    for (int mi = 0; mi < 4; mi++) {
        int r0 = rowBase + warpM * 64 + mi * 16 + (lane >> 2);
        #pragma unroll
        for (int ni = 0; ni < NI; ni++) {
            int cc = colBase + warpN * WN + ni * 8 + (lane & 3) * 2;
            float2 v0 = make_float2(acc[mi][ni][0], acc[mi][ni][1]);
            float2 v1 = make_float2(acc[mi][ni][2], acc[mi][ni][3]);
            *reinterpret_cast<float2*>(C + (size_t)r0 * ldc + cc) = v0;
            *reinterpret_cast<float2*>(C + (size_t)(r0 + 8) * ldc + cc) = v1;
        }
    }
}

// ---------------- h_in + split into A2 ----------------
__global__ void hin_kernel(const float* __restrict__ adj, int v) {
    int b = blockIdx.x;
    int j = threadIdx.x;     // 0..511
    __shared__ float sa[MAXN];
    if (j < MAXN) sa[j] = adj[(b * MAXN + v) * MAXN + j];
    __syncthreads();
    float acc = 0.f;
    if (j < HS) {
        const float* Mb = d_M + (size_t)b * MAXN * HS + j;
        for (int n = 0; n < v; n++) {
            float a = sa[n];
            if (a != 0.f) acc += a * Mb[n * HS];
        }
        d_Hin[b * HP + j] = acc;
    }
    __nv_bfloat16 hi, lo;
    if (j < HS) split_bf16(acc, hi, lo);
    else { hi = __float2bfloat16(0.f); lo = hi; }
    __nv_bfloat16* a2 = d_A2 + (size_t)b * KE;
    a2[j] = hi; a2[HP + j] = hi; a2[2 * HP + j] = lo;
}

// ---------------- GRU epilogue: hv ; split hv into A2 ----------------
__global__ void epi1_kernel(const int* __restrict__ node_types,
                            const float* __restrict__ w_ih,
                            const float* __restrict__ b_ih,
                            const float* __restrict__ b_hh, int v) {
    int b = blockIdx.x;
    int j = threadIdx.x;     // 0..511
    __shared__ int st;
    if (j == 0) st = node_types[b * MAXN + v];
    __syncthreads();
    float hv = 0.f;
    if (j < HS) {
        int t = st;
        float ir  = w_ih[(size_t)j * NVTT + t]              + b_ih[j];
        float iz  = w_ih[(size_t)(j + HS) * NVTT + t]       + b_ih[j + HS];
        float inn = w_ih[(size_t)(j + 2 * HS) * NVTT + t]   + b_ih[j + 2 * HS];
        const float* gh = d_GH + (size_t)b * N1P;
        float hr = gh[j]            + b_hh[j];
        float hz = gh[512 + j]      + b_hh[j + HS];
        float hn = gh[1024 + j]     + b_hh[j + 2 * HS];
        float r = 1.f / (1.f + __expf(-(ir + hr)));
        float z = 1.f / (1.f + __expf(-(iz + hz)));
        float n = tanhf(inn + r * hn);
        float h = d_Hin[b * HP + j];
        hv = (1.f - z) * n + z * h;
        d_hv[b * HP + j] = hv;
    }
    __nv_bfloat16 hi, lo;
    if (j < HS) split_bf16(hv, hi, lo);
    else { hi = __float2bfloat16(0.f); lo = hi; }
    __nv_bfloat16* a2 = d_A2 + (size_t)b * KE;
    a2[j] = hi; a2[HP + j] = hi; a2[2 * HP + j] = lo;
}

// ---------------- gate/map epilogue: M[b,v,:] ----------------
__global__ void epi2_kernel(const float* __restrict__ gate_w,
                            const float* __restrict__ gate_b,
                            const float* __restrict__ map_w, int v) {
    int b = blockIdx.x;
    int j = threadIdx.x;
    if (j >= HS) return;
    const float* gm = d_GM + (size_t)b * N2P;
    float g = gm[j] + gate_w[(size_t)j * VS + HS + v] + gate_b[j];
    g = 1.f / (1.f + __expf(-g));
    float m = gm[512 + j] + map_w[(size_t)j * VS + HS + v];
    d_M[((size_t)b * MAXN + v) * HS + j] = g * m;
}

// ---------------- final head ----------------
__global__ void final_kernel(const float* __restrict__ fc1_w,
                             const float* __restrict__ fc1_b,
                             const float* __restrict__ fc2_w,
                             const float* __restrict__ fc2_b,
                             float* __restrict__ out) {
    int b = blockIdx.x;
    __shared__ float sh[HS];
    for (int j = threadIdx.x; j < HS; j += blockDim.x)
        sh[j] = d_hv[(size_t)b * HP + j];
    __syncthreads();
    int o = threadIdx.x;
    if (o < 2 * NZ) {
        const float* w;
        float bias;
        if (o < NZ) { w = fc1_w + (size_t)o * HS;        bias = fc1_b[o]; }
        else        { w = fc2_w + (size_t)(o - NZ) * HS; bias = fc2_b[o - NZ]; }
        float acc = bias;
        #pragma unroll 4
        for (int k = 0; k < HS; k++) acc += w[k] * sh[k];
        out[(size_t)b * (2 * NZ) + o] = acc;
    }
}

// ---------------- launch ----------------
extern "C" void kernel_launch(void* const* d_in, const int* in_sizes, int n_in,
                              void* d_out, int out_size) {
    const int*   node_types = (const int*)  d_in[0];
    const float* adj        = (const float*)d_in[1];
    const float* w_ih       = (const float*)d_in[2];
    const float* w_hh       = (const float*)d_in[3];
    const float* b_ih       = (const float*)d_in[4];
    const float* b_hh       = (const float*)d_in[5];
    const float* gate_w     = (const float*)d_in[6];
    const float* gate_b     = (const float*)d_in[7];
    const float* map_w      = (const float*)d_in[8];
    const float* fc1_w      = (const float*)d_in[9];
    const float* fc1_b      = (const float*)d_in[10];
    const float* fc2_w      = (const float*)d_in[11];
    const float* fc2_b      = (const float*)d_in[12];
    float* out = (float*)d_out;

    void *pA2_, *pWhh2_, *pW22_, *pGH_, *pGM_;
    cudaGetSymbolAddress(&pA2_,   d_A2);
    cudaGetSymbolAddress(&pWhh2_, d_Whh2);
    cudaGetSymbolAddress(&pW22_,  d_W22);
    cudaGetSymbolAddress(&pGH_,   d_GH);
    cudaGetSymbolAddress(&pGM_,   d_GM);
    const __nv_bfloat16* pA2   = (const __nv_bfloat16*)pA2_;
    const __nv_bfloat16* pWhh2 = (const __nv_bfloat16*)pWhh2_;
    const __nv_bfloat16* pW22  = (const __nv_bfloat16*)pW22_;
    float* pGH = (float*)pGH_;
    float* pGM = (float*)pGM_;

    const int smem1 = 3 * (128 + 192) * 128;   // 120 KB
    const int smem2 = 3 * (128 + 128) * 128;   // 96 KB
    cudaFuncSetAttribute(gemm_tc<192>, cudaFuncAttributeMaxDynamicSharedMemorySize, smem1);
    cudaFuncSetAttribute(gemm_tc<128>, cudaFuncAttributeMaxDynamicSharedMemorySize, smem2);

    pack_whh_kernel<<<(N1P * KE + 255) / 256, 256>>>(w_hh);
    pack_w2_kernel<<<(N2P * KE + 255) / 256, 256>>>(gate_w, map_w);

    dim3 g1(N1P / 192, BB / 128);   // 8 x 16 = 128 blocks
    dim3 g2(N2P / 128, BB / 128);   // 8 x 16 = 128 blocks

    for (int v = 0; v < MAXN; v++) {
        hin_kernel<<<BB, 512>>>(adj, v);
        gemm_tc<192><<<g1, 256, smem1>>>(pA2, pWhh2, pGH, N1P);
        epi1_kernel<<<BB, 512>>>(node_types, w_ih, b_ih, b_hh, v);
        gemm_tc<128><<<g2, 256, smem2>>>(pA2, pW22, pGM, N2P);
        epi2_kernel<<<BB, 512>>>(gate_w, gate_b, map_w, v);
    }
    final_kernel<<<BB, 128>>>(fc1_w, fc1_b, fc2_w, fc2_b, out);
}